// round 14
// baseline (speedup 1.0000x reference)
#include <cuda_runtime.h>
#include <cuda_bf16.h>
#include <cstdint>

#define HH 48
#define WW 160
#define BB 32
#define CIn 32
#define NG 160
#define CO_ 64
#define HOo 24
#define WOo 80
#define CELLSZ 1024
#define DIRSZ (HH*WW*CELLSZ)
#define NPAIR 24

__device__ __nv_bfloat16 g_xhi[HH*WW*BB*CIn];   // [r][c][b][ci]
__device__ __nv_bfloat16 g_xmi[HH*WW*BB*CIn];
__device__ __nv_bfloat16 g_xlo[HH*WW*BB*CIn];
__device__ float    g_hd [4*DIRSZ];             // scan coords, [b*32+ch]
__device__ float    g_cd [4*DIRSZ];             // boundary rows
__device__ unsigned g_prog[4*NPAIR];
__device__ float    g_y [BB*CO_*HOo*WOo];
__device__ float    g_ps1[BB*HOo*CO_];
__device__ float    g_ps2[BB*HOo*CO_];
__device__ float    g_sc[CO_];
__device__ float    g_sh[CO_];

__device__ __forceinline__ unsigned ld_acq(const unsigned* p) {
    unsigned v; asm volatile("ld.acquire.gpu.global.u32 %0, [%1];" : "=r"(v) : "l"(p) : "memory"); return v;
}
__device__ __forceinline__ void st_rel(unsigned* p, unsigned v) {
    asm volatile("st.release.gpu.global.u32 [%0], %1;" :: "l"(p), "r"(v) : "memory");
}
__device__ __forceinline__ float fsigmoid(float x) { float e = __expf(-x); return __fdividef(1.0f, 1.0f + e); }
__device__ __forceinline__ float ftanh(float x) {
    float ax = fabsf(x); float e = __expf(-2.0f*ax);
    return copysignf(__fdividef(1.0f - e, 1.0f + e), x);
}
__device__ __forceinline__ void split3(float v, unsigned short& h, unsigned short& m, unsigned short& l) {
    __nv_bfloat16 b0 = __float2bfloat16(v);
    float r1 = v - __bfloat162float(b0);
    __nv_bfloat16 b1 = __float2bfloat16(r1);
    __nv_bfloat16 b2 = __float2bfloat16(r1 - __bfloat162float(b1));
    h = __bfloat16_as_ushort(b0); m = __bfloat16_as_ushort(b1); l = __bfloat16_as_ushort(b2);
}
__device__ __forceinline__ uint32_t smem_u32(const void* p) {
    uint32_t a; asm("{ .reg .u64 t; cvta.to.shared.u64 t, %1; cvt.u32.u64 %0, t; }" : "=r"(a) : "l"(p)); return a;
}
__device__ __forceinline__ uint4 pk8(const unsigned short* s) {
    return make_uint4((unsigned)s[0]|((unsigned)s[1]<<16), (unsigned)s[2]|((unsigned)s[3]<<16),
                      (unsigned)s[4]|((unsigned)s[5]<<16), (unsigned)s[6]|((unsigned)s[7]<<16));
}
#define LDSM4(r, addr) \
    asm volatile("ldmatrix.sync.aligned.m8n8.x4.shared.b16 {%0,%1,%2,%3}, [%4];" \
        : "=r"((r)[0]), "=r"((r)[1]), "=r"((r)[2]), "=r"((r)[3]) : "r"(addr))
#define MMA(d, a, b0, b1) \
    asm volatile("mma.sync.aligned.m16n8k16.row.col.f32.bf16.bf16.f32 " \
        "{%0,%1,%2,%3}, {%4,%5,%6,%7}, {%8,%9}, {%0,%1,%2,%3};" \
        : "+f"((d)[0]), "+f"((d)[1]), "+f"((d)[2]), "+f"((d)[3]) \
        : "r"((a)[0]), "r"((a)[1]), "r"((a)[2]), "r"((a)[3]), "r"(b0), "r"(b1))

__global__ void prep_kernel(const float* __restrict__ x) {
    int t = blockIdx.x * blockDim.x + threadIdx.x;   // 7680x256, 4 elems each
    if (t < 4*NPAIR) g_prog[t] = 0;
    int i0 = t*4;
    int ci = i0 & 31, b = (i0>>5) & 31, c = (i0>>10) % WW, r = i0/(WW*CELLSZ);
    const float* xp = x + (((size_t)(b*CIn + ci))*HH + r)*WW + c;
    const size_t s = (size_t)HH*WW;
    unsigned short h[4], m[4], l[4];
    #pragma unroll
    for (int j = 0; j < 4; ++j) split3(xp[j*s], h[j], m[j], l[j]);
    *(uint2*)(g_xhi + i0) = make_uint2((unsigned)h[0]|((unsigned)h[1]<<16), (unsigned)h[2]|((unsigned)h[3]<<16));
    *(uint2*)(g_xmi + i0) = make_uint2((unsigned)m[0]|((unsigned)m[1]<<16), (unsigned)m[2]|((unsigned)m[3]<<16));
    *(uint2*)(g_xlo + i0) = make_uint2((unsigned)l[0]|((unsigned)l[1]<<16), (unsigned)l[2]|((unsigned)l[3]<<16));
}
__global__ void noop_kernel() {}

// ---------------- MDLSTM: 96 CTAs x 128 thr, HMMA, 3-way bf16 split ----------------
#define LDA 208          // bytes per row (104 bf16)
#define SM_AH 0
#define SM_AM 13312
#define SM_AL 26624
#define SM_WH 39936
#define SM_WM 73216
#define SM_WL 106496
#define SM_CT0 139776
#define SM_CT1 143872
#define SM_TOTB 152064

__launch_bounds__(128)
__global__ void mdlstm_kernel(const float* __restrict__ Wx, const float* __restrict__ Ul,
                              const float* __restrict__ Ut, const float* __restrict__ bias) {
    extern __shared__ char smc[];
    float* Ct0 = (float*)(smc + SM_CT0);
    float* Ct1 = (float*)(smc + SM_CT1);

    const int tid = threadIdx.x, w = tid >> 5, l = tid & 31;
    const int d = blockIdx.x / NPAIR, p = blockIdx.x % NPAIR;
    const bool flipH = (d >= 2), flipW = (d & 1);
    const int r0 = 2*p, r1 = 2*p + 1;
    const int r0o = flipH ? (HH-1-r0) : r0;
    const int r1o = flipH ? (HH-1-r1) : r1;

    // zero A tiles (3 x 13312 B) + Ct (12288 B)
    for (int i = tid; i < 9984; i += 128) ((unsigned*)smc)[i] = 0u;
    for (int i = tid; i < 3072; i += 128) Ct0[i] = 0.0f;
    // stage W 3-way split: [n][k], pitch 104
    for (int idx = tid; idx < NG*96; idx += 128) {
        int n = idx/96, k = idx%96;
        float wv = (k < 32) ? Wx[(d*32+k)*NG + n] : (k < 64) ? Ul[(d*32+k-32)*NG + n]
                 : Ut[(d*32+k-64)*NG + n];
        unsigned short h, m, lo; split3(wv, h, m, lo);
        *(unsigned short*)(smc + SM_WH + n*LDA + k*2) = h;
        *(unsigned short*)(smc + SM_WM + n*LDA + k*2) = m;
        *(unsigned short*)(smc + SM_WL + n*LDA + k*2) = lo;
    }
    __syncthreads();

    // bias fragment
    float breg[20][2];
    #pragma unroll
    for (int nt = 0; nt < 20; ++nt) {
        breg[nt][0] = bias[d*NG + nt*8 + (l&3)*2];
        breg[nt][1] = bias[d*NG + nt*8 + (l&3)*2 + 1];
    }
    const uint32_t smb = smem_u32(smc);
    const uint32_t aAH = smb + SM_AH + (16*w + (l&15))*LDA + (l>>4)*16;
    const uint32_t aAM = aAH + (SM_AM - SM_AH);
    const uint32_t aAL = aAH + (SM_AL - SM_AH);
    const uint32_t bBH = smb + SM_WH + (l&15)*LDA + (l>>4)*16;
    const uint32_t bBM = bBH + (SM_WM - SM_WH);
    const uint32_t bBL = bBH + (SM_WL - SM_WH);

    const int cell = w >> 1;
    unsigned* myflag = &g_prog[d*NPAIR + p];
    const unsigned* upflag = (p > 0) ? &g_prog[d*NPAIR + p - 1] : 0;
    float creg[16];
    #pragma unroll
    for (int i = 0; i < 16; ++i) creg[i] = 0.0f;

    for (int t = 0; t <= WW; ++t) {
        // ---------- staging ----------
        {
            int row = tid >> 1, half = tid & 1;
            int cr = row >> 5, brow = row & 31;
            bool act = cr ? (t >= 1) : (t < WW);
            uint4 xh0, xh1, xm0, xm1, xl0, xl1;
            if (act) {
                int cc = cr ? t-1 : t;
                int c = flipW ? (WW-1-cc) : cc;
                size_t base = (((size_t)((cr ? r1o : r0o)*WW + c))*32 + brow)*32 + half*16;
                xh0 = *(const uint4*)(g_xhi + base); xh1 = *(const uint4*)(g_xhi + base + 8);
                xm0 = *(const uint4*)(g_xmi + base); xm1 = *(const uint4*)(g_xmi + base + 8);
                xl0 = *(const uint4*)(g_xlo + base); xl1 = *(const uint4*)(g_xlo + base + 8);
            }
            if (t < WW && p > 0) {
                if (tid == 0) { while ((int)ld_acq(upflag) < t + 1) { } }
                __syncthreads();
                size_t hb = (((size_t)(d*HH + r0 - 1))*WW + t)*CELLSZ;
                int sb = tid >> 2, g8 = (tid & 3)*8;
                const float* hp = g_hd + hb + sb*32 + g8;
                unsigned short sh[8], sm[8], sl[8];
                #pragma unroll
                for (int j = 0; j < 8; ++j) split3(hp[j], sh[j], sm[j], sl[j]);
                *(uint4*)(smc + SM_AH + sb*LDA + (64+g8)*2) = pk8(sh);
                *(uint4*)(smc + SM_AM + sb*LDA + (64+g8)*2) = pk8(sm);
                *(uint4*)(smc + SM_AL + sb*LDA + (64+g8)*2) = pk8(sl);
                const float* cp = g_cd + hb + sb*32 + g8;
                *(float4*)(Ct0 + sb*32 + g8)     = *(const float4*)cp;
                *(float4*)(Ct0 + sb*32 + g8 + 4) = *(const float4*)(cp + 4);
            }
            if (act) {
                char* da = smc + SM_AH + row*LDA + half*32;
                *(uint4*)da = xh0; *(uint4*)(da + 16) = xh1;
                da = smc + SM_AM + row*LDA + half*32;
                *(uint4*)da = xm0; *(uint4*)(da + 16) = xm1;
                da = smc + SM_AL + row*LDA + half*32;
                *(uint4*)da = xl0; *(uint4*)(da + 16) = xl1;
            }
        }
        __syncthreads();

        // ---------- GEMM: 6-term 3-way bf16 split on HMMA ----------
        float acc[20][4];
        #pragma unroll
        for (int nt = 0; nt < 20; ++nt) {
            acc[nt][0] = breg[nt][0]; acc[nt][2] = breg[nt][0];
            acc[nt][1] = breg[nt][1]; acc[nt][3] = breg[nt][1];
        }
        #pragma unroll
        for (int kt = 0; kt < 6; ++kt) {
            uint32_t ah[4], am[4], al[4];
            LDSM4(ah, aAH + kt*32);
            LDSM4(am, aAM + kt*32);
            LDSM4(al, aAL + kt*32);
            #pragma unroll
            for (int np = 0; np < 10; ++np) {
                uint32_t bh[4], bm[4], bl[4];
                LDSM4(bh, bBH + np*(16*LDA) + kt*32);
                LDSM4(bm, bBM + np*(16*LDA) + kt*32);
                LDSM4(bl, bBL + np*(16*LDA) + kt*32);
                MMA(acc[2*np],   ah, bh[0], bh[2]);
                MMA(acc[2*np],   ah, bm[0], bm[2]);
                MMA(acc[2*np],   am, bh[0], bh[2]);
                MMA(acc[2*np],   ah, bl[0], bl[2]);
                MMA(acc[2*np],   am, bm[0], bm[2]);
                MMA(acc[2*np],   al, bh[0], bh[2]);
                MMA(acc[2*np+1], ah, bh[1], bh[3]);
                MMA(acc[2*np+1], ah, bm[1], bm[3]);
                MMA(acc[2*np+1], am, bh[1], bh[3]);
                MMA(acc[2*np+1], ah, bl[1], bl[3]);
                MMA(acc[2*np+1], am, bm[1], bm[3]);
                MMA(acc[2*np+1], al, bh[1], bh[3]);
            }
        }
        __syncthreads();   // mma done before gates rewrite A h-slots

        // ---------- gates (register-resident z and c) ----------
        {
            bool act = cell ? (t >= 1) : (t < WW);
            if (act) {
                int col = cell ? t-1 : t;
                size_t gb = (((size_t)(d*HH + (cell ? r1 : r0)))*WW + col)*CELLSZ;
                float* ctw = Ct1 + (t & 1)*1024;
                const float* ctr = cell ? (Ct1 + ((t + 1) & 1)*1024) : Ct0;
                #pragma unroll
                for (int h = 0; h < 2; ++h) {
                    int b = (w*16 + (l>>2) + 8*h) & 31;
                    #pragma unroll
                    for (int tile = 0; tile < 4; ++tile) {
                        int chb = (l&3)*2 + 8*tile;
                        float2 ct = *(const float2*)(ctr + b*32 + chb);
                        float cv[2], hv[2];
                        #pragma unroll
                        for (int par = 0; par < 2; ++par) {
                            int ri = 2*h + par;
                            float zi  = acc[tile][ri],    zfl = acc[tile+4][ri];
                            float zft = acc[tile+8][ri],  zo  = acc[tile+12][ri];
                            float zg  = acc[tile+16][ri];
                            float ctp = par ? ct.y : ct.x;
                            int idx = h*8 + tile*2 + par;
                            float cs = fsigmoid(zfl)*creg[idx] + fsigmoid(zft)*ctp
                                     + fsigmoid(zi)*ftanh(zg);
                            float hh = fsigmoid(zo)*ftanh(cs);
                            creg[idx] = cs; cv[par] = cs; hv[par] = hh;
                        }
                        unsigned short h0[3], h1[3];
                        split3(hv[0], h0[0], h0[1], h0[2]);
                        split3(hv[1], h1[0], h1[1], h1[2]);
                        unsigned u[3];
                        #pragma unroll
                        for (int q = 0; q < 3; ++q) u[q] = (unsigned)h0[q] | ((unsigned)h1[q] << 16);
                        if (cell == 0) {
                            *(unsigned*)(smc + SM_AH + b*LDA + (32+chb)*2)      = u[0]; // h_left r0
                            *(unsigned*)(smc + SM_AM + b*LDA + (32+chb)*2)      = u[1];
                            *(unsigned*)(smc + SM_AL + b*LDA + (32+chb)*2)      = u[2];
                            *(unsigned*)(smc + SM_AH + (32+b)*LDA + (64+chb)*2) = u[0]; // h_top r1
                            *(unsigned*)(smc + SM_AM + (32+b)*LDA + (64+chb)*2) = u[1];
                            *(unsigned*)(smc + SM_AL + (32+b)*LDA + (64+chb)*2) = u[2];
                            *(float2*)(ctw + b*32 + chb) = make_float2(cv[0], cv[1]);
                            *(float2*)(g_hd + gb + b*32 + chb) = make_float2(hv[0], hv[1]);
                        } else {
                            *(unsigned*)(smc + SM_AH + (32+b)*LDA + (32+chb)*2) = u[0]; // h_left r1
                            *(unsigned*)(smc + SM_AM + (32+b)*LDA + (32+chb)*2) = u[1];
                            *(unsigned*)(smc + SM_AL + (32+b)*LDA + (32+chb)*2) = u[2];
                            *(float2*)(g_hd + gb + b*32 + chb) = make_float2(hv[0], hv[1]);
                            *(float2*)(g_cd + gb + b*32 + chb) = make_float2(cv[0], cv[1]);
                        }
                    }
                }
            }
        }
        __syncthreads();
        if (tid == 0 && t >= 1) { __threadfence(); st_rel(myflag, (unsigned)t); }
    }
}

__launch_bounds__(256, 2)
__global__ void conv_kernel(const float* __restrict__ conv_w, const float* __restrict__ conv_b) {
    extern __shared__ float sm2[];
    float* Hs = sm2;
    float* Wt = sm2 + 10240;
    const int ho = blockIdx.x, b = blockIdx.y, tid = threadIdx.x;
    for (int i = tid; i < 128*64; i += 256) { int co = i & 63, q = i >> 6; Wt[i] = conv_w[co*128 + q]; }
    for (int idx = tid; idx < 2*WW*32; idx += 256) {
        int cl = idx & 31, c = (idx >> 5) % WW, rr = idx/(WW*32), rg = 2*ho + rr;
        float v = 0.0f;
        #pragma unroll
        for (int d = 0; d < 4; ++d) {
            int Rd = (d >= 2) ? (HH-1-rg) : rg;
            int Cd = (d & 1) ? (WW-1-c) : c;
            v += g_hd[(((size_t)(d*HH + Rd))*WW + Cd)*CELLSZ + b*32 + cl];
        }
        Hs[idx] = v;
    }
    __syncthreads();
    const int co = tid >> 2, ws = tid & 3;
    float acc[20];
    #pragma unroll
    for (int j = 0; j < 20; ++j) acc[j] = 0.0f;
    for (int cl = 0; cl < 32; ++cl) {
        float w00 = Wt[(cl*4+0)*64+co], w01 = Wt[(cl*4+1)*64+co];
        float w10 = Wt[(cl*4+2)*64+co], w11 = Wt[(cl*4+3)*64+co];
        #pragma unroll
        for (int j = 0; j < 20; ++j) {
            int c0 = 2*(j*4 + ws);
            acc[j] += Hs[c0*32+cl]*w00 + Hs[(c0+1)*32+cl]*w01 + Hs[(WW+c0)*32+cl]*w10 + Hs[(WW+c0+1)*32+cl]*w11;
        }
    }
    float bb = 4.0f*conv_b[co], s1 = 0.0f, s2 = 0.0f;
    float* ybase = g_y + (((size_t)b*CO_ + co)*HOo + ho)*WOo;
    #pragma unroll
    for (int j = 0; j < 20; ++j) {
        float y = ftanh(acc[j] + bb);
        ybase[j*4 + ws] = y; s1 += y; s2 += y*y;
    }
    s1 += __shfl_down_sync(0xffffffffu, s1, 1, 4); s1 += __shfl_down_sync(0xffffffffu, s1, 2, 4);
    s2 += __shfl_down_sync(0xffffffffu, s2, 1, 4); s2 += __shfl_down_sync(0xffffffffu, s2, 2, 4);
    if (ws == 0) { int pp = b*HOo + ho; g_ps1[pp*CO_ + co] = s1; g_ps2[pp*CO_ + co] = s2; }
}

__global__ void reduce_kernel(const float* __restrict__ gamma, const float* __restrict__ beta) {
    __shared__ float sh1[256], sh2[256];
    const int co = blockIdx.x, t = threadIdx.x;
    float s1 = 0.0f, s2 = 0.0f;
    for (int p = t; p < BB*HOo; p += 256) { s1 += g_ps1[p*CO_ + co]; s2 += g_ps2[p*CO_ + co]; }
    sh1[t] = s1; sh2[t] = s2;
    __syncthreads();
    for (int s = 128; s > 0; s >>= 1) {
        if (t < s) { sh1[t] += sh1[t+s]; sh2[t] += sh2[t+s]; }
        __syncthreads();
    }
    if (t == 0) {
        const float N = (float)(BB*HOo*WOo);
        float mean = sh1[0]/N, var = sh2[0]/N - mean*mean;
        float sc = gamma[co]*rsqrtf(var + 1e-5f);
        g_sc[co] = sc; g_sh[co] = beta[co] - mean*sc;
    }
}

__global__ void norm_kernel(float* __restrict__ out) {
    int t = blockIdx.x*blockDim.x + threadIdx.x;
    int i0 = t*4, co = (i0/(HOo*WOo)) & 63;
    float sc = g_sc[co], sh = g_sh[co];
    float4 v = *(const float4*)(g_y + i0);
    v.x = v.x*sc + sh; v.y = v.y*sc + sh; v.z = v.z*sc + sh; v.w = v.w*sc + sh;
    *(float4*)(out + i0) = v;
}

extern "C" void kernel_launch(void* const* d_in, const int* in_sizes, int n_in,
                              void* d_out, int out_size) {
    (void)in_sizes; (void)n_in; (void)out_size;
    const float* x      = (const float*)d_in[0];
    const float* Wx     = (const float*)d_in[1];
    const float* Ul     = (const float*)d_in[2];
    const float* Ut     = (const float*)d_in[3];
    const float* bias   = (const float*)d_in[4];
    const float* conv_w = (const float*)d_in[5];
    const float* conv_b = (const float*)d_in[6];
    const float* gamma  = (const float*)d_in[7];
    const float* beta   = (const float*)d_in[8];
    float* out = (float*)d_out;

    cudaFuncSetAttribute(mdlstm_kernel, cudaFuncAttributeMaxDynamicSharedMemorySize, SM_TOTB);
    cudaFuncSetAttribute(conv_kernel,   cudaFuncAttributeMaxDynamicSharedMemorySize, (10240+8192)*4);

    prep_kernel<<<7680, 256>>>(x);
    noop_kernel<<<1, 32>>>();
    noop_kernel<<<1, 32>>>();
    mdlstm_kernel<<<4*NPAIR, 128, SM_TOTB>>>(Wx, Ul, Ut, bias);
    conv_kernel<<<dim3(HOo, BB), 256, (10240+8192)*4>>>(conv_w, conv_b);
    reduce_kernel<<<CO_, 256>>>(gamma, beta);
    norm_kernel<<<3840, 256>>>(out);
}

// round 15
// speedup vs baseline: 1.1680x; 1.1680x over previous
#include <cuda_runtime.h>
#include <cuda_bf16.h>
#include <cstdint>

#define HH 48
#define WW 160
#define BB 32
#define CIn 32
#define NG 160
#define CO_ 64
#define HOo 24
#define WOo 80
#define CELLSZ 1024
#define DIRSZ (HH*WW*CELLSZ)
#define NPAIR 24

__device__ __nv_bfloat16 g_xhi[HH*WW*BB*CIn];   // [r][c][b][ci]
__device__ __nv_bfloat16 g_xmi[HH*WW*BB*CIn];
__device__ __nv_bfloat16 g_xlo[HH*WW*BB*CIn];
__device__ float    g_hd [4*DIRSZ];             // scan coords, [b*32+ch]
__device__ float    g_cd [4*DIRSZ];             // boundary rows
__device__ unsigned g_prog[4*NPAIR];
__device__ float    g_y [BB*CO_*HOo*WOo];
__device__ float    g_ps1[BB*HOo*CO_];
__device__ float    g_ps2[BB*HOo*CO_];
__device__ float    g_sc[CO_];
__device__ float    g_sh[CO_];

__device__ __forceinline__ unsigned ld_acq(const unsigned* p) {
    unsigned v; asm volatile("ld.acquire.gpu.global.u32 %0, [%1];" : "=r"(v) : "l"(p) : "memory"); return v;
}
__device__ __forceinline__ void st_rel(unsigned* p, unsigned v) {
    asm volatile("st.release.gpu.global.u32 [%0], %1;" :: "l"(p), "r"(v) : "memory");
}
__device__ __forceinline__ float fsigmoid(float x) { float e = __expf(-x); return __fdividef(1.0f, 1.0f + e); }
__device__ __forceinline__ float ftanh(float x) {
    float ax = fabsf(x); float e = __expf(-2.0f*ax);
    return copysignf(__fdividef(1.0f - e, 1.0f + e), x);
}
__device__ __forceinline__ void split3(float v, unsigned short& h, unsigned short& m, unsigned short& l) {
    __nv_bfloat16 b0 = __float2bfloat16(v);
    float r1 = v - __bfloat162float(b0);
    __nv_bfloat16 b1 = __float2bfloat16(r1);
    __nv_bfloat16 b2 = __float2bfloat16(r1 - __bfloat162float(b1));
    h = __bfloat16_as_ushort(b0); m = __bfloat16_as_ushort(b1); l = __bfloat16_as_ushort(b2);
}
__device__ __forceinline__ uint32_t smem_u32(const void* p) {
    uint32_t a; asm("{ .reg .u64 t; cvta.to.shared.u64 t, %1; cvt.u32.u64 %0, t; }" : "=r"(a) : "l"(p)); return a;
}
#define LDSM4(r, addr) \
    asm volatile("ldmatrix.sync.aligned.m8n8.x4.shared.b16 {%0,%1,%2,%3}, [%4];" \
        : "=r"((r)[0]), "=r"((r)[1]), "=r"((r)[2]), "=r"((r)[3]) : "r"(addr))
#define MMA(d, a, b0, b1) \
    asm volatile("mma.sync.aligned.m16n8k16.row.col.f32.bf16.bf16.f32 " \
        "{%0,%1,%2,%3}, {%4,%5,%6,%7}, {%8,%9}, {%0,%1,%2,%3};" \
        : "+f"((d)[0]), "+f"((d)[1]), "+f"((d)[2]), "+f"((d)[3]) \
        : "r"((a)[0]), "r"((a)[1]), "r"((a)[2]), "r"((a)[3]), "r"(b0), "r"(b1))

__global__ void prep_kernel(const float* __restrict__ x) {
    int t = blockIdx.x * blockDim.x + threadIdx.x;
    if (t < 4*NPAIR) g_prog[t] = 0;
    int i0 = t*4;
    int ci = i0 & 31, b = (i0>>5) & 31, c = (i0>>10) % WW, r = i0/(WW*CELLSZ);
    const float* xp = x + (((size_t)(b*CIn + ci))*HH + r)*WW + c;
    const size_t s = (size_t)HH*WW;
    unsigned short h[4], m[4], l[4];
    #pragma unroll
    for (int j = 0; j < 4; ++j) split3(xp[j*s], h[j], m[j], l[j]);
    *(uint2*)(g_xhi + i0) = make_uint2((unsigned)h[0]|((unsigned)h[1]<<16), (unsigned)h[2]|((unsigned)h[3]<<16));
    *(uint2*)(g_xmi + i0) = make_uint2((unsigned)m[0]|((unsigned)m[1]<<16), (unsigned)m[2]|((unsigned)m[3]<<16));
    *(uint2*)(g_xlo + i0) = make_uint2((unsigned)l[0]|((unsigned)l[1]<<16), (unsigned)l[2]|((unsigned)l[3]<<16));
}
__global__ void noop_kernel() {}

// ---------------- MDLSTM: 96 CTAs x 256 thr, HMMA, 3-way bf16 split ----------------
#define LDA 208          // bytes per row (104 bf16)
#define ZP  166          // Zs pitch (floats)
#define SM_AH 0
#define SM_AM 13312
#define SM_AL 26624
#define SM_WH 39936
#define SM_WM 73216
#define SM_WL 106496
#define SM_ZS 139776
#define SM_CT0 182272
#define SM_TOTB 186368

__launch_bounds__(256)
__global__ void mdlstm_kernel(const float* __restrict__ Wx, const float* __restrict__ Ul,
                              const float* __restrict__ Ut, const float* __restrict__ bias) {
    extern __shared__ char smc[];
    float* Zs  = (float*)(smc + SM_ZS);
    float* Ct0 = (float*)(smc + SM_CT0);

    const int tid = threadIdx.x, w = tid >> 5, l = tid & 31;
    const int d = blockIdx.x / NPAIR, p = blockIdx.x % NPAIR;
    const bool flipH = (d >= 2), flipW = (d & 1);
    const int r0 = 2*p, r1 = 2*p + 1;
    const int r0o = flipH ? (HH-1-r0) : r0;
    const int r1o = flipH ? (HH-1-r1) : r1;

    // zero A tiles + Ct0
    for (int i = tid; i < 9984; i += 256) ((unsigned*)smc)[i] = 0u;
    for (int i = tid; i < 1024; i += 256) Ct0[i] = 0.0f;
    // stage W 3-way split: [n][k], pitch 104
    for (int idx = tid; idx < NG*96; idx += 256) {
        int n = idx/96, k = idx%96;
        float wv = (k < 32) ? Wx[(d*32+k)*NG + n] : (k < 64) ? Ul[(d*32+k-32)*NG + n]
                 : Ut[(d*32+k-64)*NG + n];
        unsigned short h, m, lo; split3(wv, h, m, lo);
        *(unsigned short*)(smc + SM_WH + n*LDA + k*2) = h;
        *(unsigned short*)(smc + SM_WM + n*LDA + k*2) = m;
        *(unsigned short*)(smc + SM_WL + n*LDA + k*2) = lo;
    }
    __syncthreads();

    // GEMM map: warp w -> rows 16*(w&3), n-half (w>>2)*80
    const int rowg  = (w & 3) * 16;
    const int nbase = (w >> 2) * 80;
    float breg[10][2];
    #pragma unroll
    for (int nt = 0; nt < 10; ++nt) {
        breg[nt][0] = bias[d*NG + nbase + nt*8 + (l&3)*2];
        breg[nt][1] = bias[d*NG + nbase + nt*8 + (l&3)*2 + 1];
    }
    const uint32_t smb = smem_u32(smc);
    const uint32_t aAH = smb + SM_AH + (rowg + (l&15))*LDA + (l>>4)*16;
    const uint32_t aAM = aAH + (SM_AM - SM_AH);
    const uint32_t aAL = aAH + (SM_AL - SM_AH);
    const uint32_t bBH = smb + SM_WH + (nbase + (l&15))*LDA + (l>>4)*16;
    const uint32_t bBM = bBH + (SM_WM - SM_WH);
    const uint32_t bBL = bBH + (SM_WL - SM_WH);

    // gates map: thread owns (b, ch0..ch0+3) for BOTH cells
    const int gb_  = tid >> 3;
    const int ch0  = (tid & 7) * 4;
    // staging map: row = tid>>2 (0..63), q = tid&3 -> 8 ci each
    const int srow = tid >> 2, sq = tid & 3;
    unsigned* myflag = &g_prog[d*NPAIR + p];
    const unsigned* upflag = (p > 0) ? &g_prog[d*NPAIR + p - 1] : 0;
    float creg0[4], creg1[4];
    #pragma unroll
    for (int i = 0; i < 4; ++i) { creg0[i] = 0.0f; creg1[i] = 0.0f; }

    for (int t = 0; t <= WW; ++t) {
        // ---------- staging ----------
        {
            int cr = srow >> 5, brow = srow & 31;
            bool act = cr ? (t >= 1) : (t < WW);
            uint4 xh, xm, xl;
            if (act) {
                int cc = cr ? t-1 : t;
                int c = flipW ? (WW-1-cc) : cc;
                size_t base = (((size_t)((cr ? r1o : r0o)*WW + c))*32 + brow)*32 + sq*8;
                xh = *(const uint4*)(g_xhi + base);
                xm = *(const uint4*)(g_xmi + base);
                xl = *(const uint4*)(g_xlo + base);
            }
            if (t < WW && p > 0) {
                if (tid == 0) { while ((int)ld_acq(upflag) < t + 1) { } }
                __syncthreads();
                size_t hb = (((size_t)(d*HH + r0 - 1))*WW + t)*CELLSZ;
                int sb = tid >> 3, g4 = (tid & 7)*4;
                const float* hp = g_hd + hb + sb*32 + g4;
                unsigned short sh[4], sm[4], sl[4];
                #pragma unroll
                for (int j = 0; j < 4; ++j) split3(hp[j], sh[j], sm[j], sl[j]);
                *(uint2*)(smc + SM_AH + sb*LDA + (64+g4)*2) =
                    make_uint2((unsigned)sh[0]|((unsigned)sh[1]<<16), (unsigned)sh[2]|((unsigned)sh[3]<<16));
                *(uint2*)(smc + SM_AM + sb*LDA + (64+g4)*2) =
                    make_uint2((unsigned)sm[0]|((unsigned)sm[1]<<16), (unsigned)sm[2]|((unsigned)sm[3]<<16));
                *(uint2*)(smc + SM_AL + sb*LDA + (64+g4)*2) =
                    make_uint2((unsigned)sl[0]|((unsigned)sl[1]<<16), (unsigned)sl[2]|((unsigned)sl[3]<<16));
                *(float4*)(Ct0 + sb*32 + g4) = *(const float4*)(g_cd + hb + sb*32 + g4);
            }
            if (act) {
                *(uint4*)(smc + SM_AH + srow*LDA + sq*16) = xh;
                *(uint4*)(smc + SM_AM + srow*LDA + sq*16) = xm;
                *(uint4*)(smc + SM_AL + srow*LDA + sq*16) = xl;
            }
        }
        __syncthreads();

        // ---------- GEMM: 6-term 3-way bf16 split on HMMA ----------
        float acc[10][4];
        #pragma unroll
        for (int nt = 0; nt < 10; ++nt) {
            acc[nt][0] = breg[nt][0]; acc[nt][2] = breg[nt][0];
            acc[nt][1] = breg[nt][1]; acc[nt][3] = breg[nt][1];
        }
        #pragma unroll
        for (int kt = 0; kt < 6; ++kt) {
            uint32_t ah[4], am[4], al[4];
            LDSM4(ah, aAH + kt*32);
            LDSM4(am, aAM + kt*32);
            LDSM4(al, aAL + kt*32);
            #pragma unroll
            for (int np = 0; np < 5; ++np) {
                uint32_t bh[4], bm[4], bl[4];
                LDSM4(bh, bBH + np*(16*LDA) + kt*32);
                LDSM4(bm, bBM + np*(16*LDA) + kt*32);
                LDSM4(bl, bBL + np*(16*LDA) + kt*32);
                MMA(acc[2*np],   ah, bh[0], bh[2]);
                MMA(acc[2*np],   ah, bm[0], bm[2]);
                MMA(acc[2*np],   am, bh[0], bh[2]);
                MMA(acc[2*np],   ah, bl[0], bl[2]);
                MMA(acc[2*np],   am, bm[0], bm[2]);
                MMA(acc[2*np],   al, bh[0], bh[2]);
                MMA(acc[2*np+1], ah, bh[1], bh[3]);
                MMA(acc[2*np+1], ah, bm[1], bm[3]);
                MMA(acc[2*np+1], am, bh[1], bh[3]);
                MMA(acc[2*np+1], ah, bl[1], bl[3]);
                MMA(acc[2*np+1], am, bm[1], bm[3]);
                MMA(acc[2*np+1], al, bh[1], bh[3]);
            }
        }
        // store z fragments to smem
        {
            int rbase = rowg + (l >> 2);
            int cb = nbase + (l & 3)*2;
            #pragma unroll
            for (int nt = 0; nt < 10; ++nt) {
                *(float2*)(Zs + rbase*ZP + cb + nt*8)     = make_float2(acc[nt][0], acc[nt][1]);
                *(float2*)(Zs + (rbase+8)*ZP + cb + nt*8) = make_float2(acc[nt][2], acc[nt][3]);
            }
        }
        __syncthreads();

        // ---------- gates: thread owns (b, ch0..ch0+3), both cells ----------
        {
            const bool act0 = (t < WW), act1 = (t >= 1);
            size_t gb0 = (((size_t)(d*HH + r0))*WW + t)*CELLSZ;
            size_t gb1 = (((size_t)(d*HH + r1))*WW + (t-1))*CELLSZ;
            float hv0[4], hv1[4];
            unsigned short s0[3][4], s1[3][4];
            // cell1 FIRST: uses creg0 = c(r0, t-1)
            if (act1) {
                const float* z = Zs + (32 + gb_)*ZP;
                #pragma unroll
                for (int j = 0; j < 4; ++j) {
                    int ch = ch0 + j;
                    float cs = fsigmoid(z[32+ch])*creg1[j] + fsigmoid(z[64+ch])*creg0[j]
                             + fsigmoid(z[ch])*ftanh(z[128+ch]);
                    float hh = fsigmoid(z[96+ch])*ftanh(cs);
                    creg1[j] = cs; hv1[j] = hh;
                    split3(hh, s1[0][j], s1[1][j], s1[2][j]);
                }
            }
            if (act0) {
                const float* z = Zs + gb_*ZP;
                #pragma unroll
                for (int j = 0; j < 4; ++j) {
                    int ch = ch0 + j;
                    float cs = fsigmoid(z[32+ch])*creg0[j] + fsigmoid(z[64+ch])*Ct0[gb_*32+ch]
                             + fsigmoid(z[ch])*ftanh(z[128+ch]);
                    float hh = fsigmoid(z[96+ch])*ftanh(cs);
                    creg0[j] = cs; hv0[j] = hh;
                    split3(hh, s0[0][j], s0[1][j], s0[2][j]);
                }
            }
            if (act1) {
                const int off = SM_AH - 0;
                #pragma unroll
                for (int q = 0; q < 3; ++q) {
                    char* base = smc + (q == 0 ? SM_AH : q == 1 ? SM_AM : SM_AL);
                    *(unsigned*)(base + (32+gb_)*LDA + (32+ch0)*2) =
                        (unsigned)s1[q][0] | ((unsigned)s1[q][1] << 16);
                    *(unsigned*)(base + (32+gb_)*LDA + (32+ch0+2)*2) =
                        (unsigned)s1[q][2] | ((unsigned)s1[q][3] << 16);
                }
                *(float4*)(g_hd + gb1 + gb_*32 + ch0) = make_float4(hv1[0], hv1[1], hv1[2], hv1[3]);
                *(float4*)(g_cd + gb1 + gb_*32 + ch0) = make_float4(creg1[0], creg1[1], creg1[2], creg1[3]);
                (void)off;
            }
            if (act0) {
                #pragma unroll
                for (int q = 0; q < 3; ++q) {
                    char* base = smc + (q == 0 ? SM_AH : q == 1 ? SM_AM : SM_AL);
                    unsigned u01 = (unsigned)s0[q][0] | ((unsigned)s0[q][1] << 16);
                    unsigned u23 = (unsigned)s0[q][2] | ((unsigned)s0[q][3] << 16);
                    *(unsigned*)(base + gb_*LDA + (32+ch0)*2)        = u01;  // h_left r0
                    *(unsigned*)(base + gb_*LDA + (32+ch0+2)*2)      = u23;
                    *(unsigned*)(base + (32+gb_)*LDA + (64+ch0)*2)   = u01;  // h_top r1
                    *(unsigned*)(base + (32+gb_)*LDA + (64+ch0+2)*2) = u23;
                }
                *(float4*)(g_hd + gb0 + gb_*32 + ch0) = make_float4(hv0[0], hv0[1], hv0[2], hv0[3]);
            }
        }
        __syncthreads();
        if (tid == 0 && t >= 1) { __threadfence(); st_rel(myflag, (unsigned)t); }
    }
}

__launch_bounds__(256, 2)
__global__ void conv_kernel(const float* __restrict__ conv_w, const float* __restrict__ conv_b) {
    extern __shared__ float sm2[];
    float* Hs = sm2;
    float* Wt = sm2 + 10240;
    const int ho = blockIdx.x, b = blockIdx.y, tid = threadIdx.x;
    for (int i = tid; i < 128*64; i += 256) { int co = i & 63, q = i >> 6; Wt[i] = conv_w[co*128 + q]; }
    for (int idx = tid; idx < 2*WW*32; idx += 256) {
        int cl = idx & 31, c = (idx >> 5) % WW, rr = idx/(WW*32), rg = 2*ho + rr;
        float v = 0.0f;
        #pragma unroll
        for (int d = 0; d < 4; ++d) {
            int Rd = (d >= 2) ? (HH-1-rg) : rg;
            int Cd = (d & 1) ? (WW-1-c) : c;
            v += g_hd[(((size_t)(d*HH + Rd))*WW + Cd)*CELLSZ + b*32 + cl];
        }
        Hs[idx] = v;
    }
    __syncthreads();
    const int co = tid >> 2, ws = tid & 3;
    float acc[20];
    #pragma unroll
    for (int j = 0; j < 20; ++j) acc[j] = 0.0f;
    for (int cl = 0; cl < 32; ++cl) {
        float w00 = Wt[(cl*4+0)*64+co], w01 = Wt[(cl*4+1)*64+co];
        float w10 = Wt[(cl*4+2)*64+co], w11 = Wt[(cl*4+3)*64+co];
        #pragma unroll
        for (int j = 0; j < 20; ++j) {
            int c0 = 2*(j*4 + ws);
            acc[j] += Hs[c0*32+cl]*w00 + Hs[(c0+1)*32+cl]*w01 + Hs[(WW+c0)*32+cl]*w10 + Hs[(WW+c0+1)*32+cl]*w11;
        }
    }
    float bb = 4.0f*conv_b[co], s1 = 0.0f, s2 = 0.0f;
    float* ybase = g_y + (((size_t)b*CO_ + co)*HOo + ho)*WOo;
    #pragma unroll
    for (int j = 0; j < 20; ++j) {
        float y = ftanh(acc[j] + bb);
        ybase[j*4 + ws] = y; s1 += y; s2 += y*y;
    }
    s1 += __shfl_down_sync(0xffffffffu, s1, 1, 4); s1 += __shfl_down_sync(0xffffffffu, s1, 2, 4);
    s2 += __shfl_down_sync(0xffffffffu, s2, 1, 4); s2 += __shfl_down_sync(0xffffffffu, s2, 2, 4);
    if (ws == 0) { int pp = b*HOo + ho; g_ps1[pp*CO_ + co] = s1; g_ps2[pp*CO_ + co] = s2; }
}

__global__ void reduce_kernel(const float* __restrict__ gamma, const float* __restrict__ beta) {
    __shared__ float sh1[256], sh2[256];
    const int co = blockIdx.x, t = threadIdx.x;
    float s1 = 0.0f, s2 = 0.0f;
    for (int p = t; p < BB*HOo; p += 256) { s1 += g_ps1[p*CO_ + co]; s2 += g_ps2[p*CO_ + co]; }
    sh1[t] = s1; sh2[t] = s2;
    __syncthreads();
    for (int s = 128; s > 0; s >>= 1) {
        if (t < s) { sh1[t] += sh1[t+s]; sh2[t] += sh2[t+s]; }
        __syncthreads();
    }
    if (t == 0) {
        const float N = (float)(BB*HOo*WOo);
        float mean = sh1[0]/N, var = sh2[0]/N - mean*mean;
        float sc = gamma[co]*rsqrtf(var + 1e-5f);
        g_sc[co] = sc; g_sh[co] = beta[co] - mean*sc;
    }
}

__global__ void norm_kernel(float* __restrict__ out) {
    int t = blockIdx.x*blockDim.x + threadIdx.x;
    int i0 = t*4, co = (i0/(HOo*WOo)) & 63;
    float sc = g_sc[co], sh = g_sh[co];
    float4 v = *(const float4*)(g_y + i0);
    v.x = v.x*sc + sh; v.y = v.y*sc + sh; v.z = v.z*sc + sh; v.w = v.w*sc + sh;
    *(float4*)(out + i0) = v;
}

extern "C" void kernel_launch(void* const* d_in, const int* in_sizes, int n_in,
                              void* d_out, int out_size) {
    (void)in_sizes; (void)n_in; (void)out_size;
    const float* x      = (const float*)d_in[0];
    const float* Wx     = (const float*)d_in[1];
    const float* Ul     = (const float*)d_in[2];
    const float* Ut     = (const float*)d_in[3];
    const float* bias   = (const float*)d_in[4];
    const float* conv_w = (const float*)d_in[5];
    const float* conv_b = (const float*)d_in[6];
    const float* gamma  = (const float*)d_in[7];
    const float* beta   = (const float*)d_in[8];
    float* out = (float*)d_out;

    cudaFuncSetAttribute(mdlstm_kernel, cudaFuncAttributeMaxDynamicSharedMemorySize, SM_TOTB);
    cudaFuncSetAttribute(conv_kernel,   cudaFuncAttributeMaxDynamicSharedMemorySize, (10240+8192)*4);

    prep_kernel<<<7680, 256>>>(x);
    noop_kernel<<<1, 32>>>();
    noop_kernel<<<1, 32>>>();
    mdlstm_kernel<<<4*NPAIR, 256, SM_TOTB>>>(Wx, Ul, Ut, bias);
    conv_kernel<<<dim3(HOo, BB), 256, (10240+8192)*4>>>(conv_w, conv_b);
    reduce_kernel<<<CO_, 256>>>(gamma, beta);
    norm_kernel<<<3840, 256>>>(out);
}